// round 2
// baseline (speedup 1.0000x reference)
#include <cuda_runtime.h>
#include <stdint.h>

#define DD 128
#define SELF_REL_IDX 1000
#define BN_EPS 1e-5f
#define MAX_N 100000

// Scratch (allocations are forbidden; __device__ globals are allowed)
__device__ float g_XW[(size_t)MAX_N * DD];
__device__ float g_stats[2 * DD];   // [0..127] sum, [128..255] sumsq

// ---------------------------------------------------------------------------
// Kernel 1: XW = x @ W  (fp32, 128x128 block tile, 8x8 per thread)
//           also out_init = 2*alpha[SELF_REL] * XW   (self-loop contribution)
// ---------------------------------------------------------------------------
__global__ void gemm_init_kernel(const float* __restrict__ x,
                                 const float* __restrict__ w,
                                 const float* __restrict__ alpha,
                                 float* __restrict__ out, int n) {
    __shared__ float xs[16][132];   // [k][row], padded to dodge bank conflicts
    __shared__ float ws[16][132];   // [k][col]
    const int tid = threadIdx.x;
    const int tx = tid & 15;        // col group
    const int ty = tid >> 4;        // row group
    const int row0 = blockIdx.x * 128;

    float acc[8][8];
#pragma unroll
    for (int i = 0; i < 8; i++)
#pragma unroll
        for (int j = 0; j < 8; j++) acc[i][j] = 0.f;

    for (int kb = 0; kb < 8; kb++) {
        // load x tile: rows [row0,row0+128), k [kb*16, kb*16+16)  -> xs[k][row]
#pragma unroll
        for (int l = 0; l < 2; l++) {
            int idx = tid + l * 256;          // 0..511
            int r   = idx >> 2;               // 0..127
            int k4  = idx & 3;                // 0..3
            float4 v = make_float4(0.f, 0.f, 0.f, 0.f);
            if (row0 + r < n)
                v = *(const float4*)&x[(size_t)(row0 + r) * DD + kb * 16 + k4 * 4];
            xs[k4 * 4 + 0][r] = v.x;
            xs[k4 * 4 + 1][r] = v.y;
            xs[k4 * 4 + 2][r] = v.z;
            xs[k4 * 4 + 3][r] = v.w;
        }
        // load w tile: rows [kb*16, +16), all 128 cols -> ws[k][col]
#pragma unroll
        for (int l = 0; l < 2; l++) {
            int idx = tid + l * 256;          // 0..511
            int kk  = idx >> 5;               // 0..15
            int c4  = idx & 31;               // 0..31
            float4 v = *(const float4*)&w[(size_t)(kb * 16 + kk) * DD + c4 * 4];
            *(float4*)&ws[kk][c4 * 4] = v;
        }
        __syncthreads();

#pragma unroll
        for (int kk = 0; kk < 16; kk++) {
            float xr[8], wr[8];
            *(float4*)&xr[0] = *(const float4*)&xs[kk][ty * 8];
            *(float4*)&xr[4] = *(const float4*)&xs[kk][ty * 8 + 4];
            *(float4*)&wr[0] = *(const float4*)&ws[kk][tx * 8];
            *(float4*)&wr[4] = *(const float4*)&ws[kk][tx * 8 + 4];
#pragma unroll
            for (int i = 0; i < 8; i++)
#pragma unroll
                for (int j = 0; j < 8; j++)
                    acc[i][j] = fmaf(xr[i], wr[j], acc[i][j]);
        }
        __syncthreads();
    }

    const float s2 = 2.0f * __ldg(&alpha[SELF_REL_IDX]);
#pragma unroll
    for (int i = 0; i < 8; i++) {
        int row = row0 + ty * 8 + i;
        if (row >= n) break;
        size_t base = (size_t)row * DD + tx * 8;
        float4 a0 = make_float4(acc[i][0], acc[i][1], acc[i][2], acc[i][3]);
        float4 a1 = make_float4(acc[i][4], acc[i][5], acc[i][6], acc[i][7]);
        *(float4*)&g_XW[base]     = a0;
        *(float4*)&g_XW[base + 4] = a1;
        float4 o0 = make_float4(s2 * a0.x, s2 * a0.y, s2 * a0.z, s2 * a0.w);
        float4 o1 = make_float4(s2 * a1.x, s2 * a1.y, s2 * a1.z, s2 * a1.w);
        *(float4*)&out[base]     = o0;
        *(float4*)&out[base + 4] = o1;
    }
}

// ---------------------------------------------------------------------------
// Kernel 2: zero the stats accumulator
// ---------------------------------------------------------------------------
__global__ void zero_stats_kernel() {
    g_stats[threadIdx.x] = 0.f;
}

// ---------------------------------------------------------------------------
// Kernel 3: edge scatter. One warp per edge:
//   out[row] += a * XW[col];  out[col] += a * XW[row]
// Vector fp32 reductions (red.global.add.v4.f32, sm_90+).
// NOTE: edge_index / edge_type arrive as int32 (JAX demotes int64 without x64).
// ---------------------------------------------------------------------------
__global__ void scatter_kernel(const int* __restrict__ ei,
                               const int* __restrict__ et,
                               const float* __restrict__ alpha,
                               float* __restrict__ out, int E) {
    int gid  = blockIdx.x * blockDim.x + threadIdx.x;
    int e    = gid >> 5;
    if (e >= E) return;
    int lane = gid & 31;

    int rw = __ldg(&ei[e]);
    int cl = __ldg(&ei[(size_t)E + e]);
    float a = __ldg(&alpha[__ldg(&et[e])]);

    const float4 vc = *(const float4*)&g_XW[(size_t)cl * DD + lane * 4];
    const float4 vr = *(const float4*)&g_XW[(size_t)rw * DD + lane * 4];

    float* pr = out + (size_t)rw * DD + lane * 4;
    float* pc = out + (size_t)cl * DD + lane * 4;

    asm volatile("red.global.add.v4.f32 [%0], {%1,%2,%3,%4};"
                 :: "l"(pr), "f"(a * vc.x), "f"(a * vc.y), "f"(a * vc.z), "f"(a * vc.w)
                 : "memory");
    asm volatile("red.global.add.v4.f32 [%0], {%1,%2,%3,%4};"
                 :: "l"(pc), "f"(a * vr.x), "f"(a * vr.y), "f"(a * vr.z), "f"(a * vr.w)
                 : "memory");
}

// ---------------------------------------------------------------------------
// Kernel 4: per-column sum / sum-of-squares
// ---------------------------------------------------------------------------
__global__ void stats_kernel(const float* __restrict__ out, int n) {
    int col = threadIdx.x;   // blockDim = 128
    float s = 0.f, sq = 0.f;
    for (int row = blockIdx.x; row < n; row += gridDim.x) {
        float v = out[(size_t)row * DD + col];
        s += v;
        sq = fmaf(v, v, sq);
    }
    atomicAdd(&g_stats[col], s);
    atomicAdd(&g_stats[DD + col], sq);
}

// ---------------------------------------------------------------------------
// Kernel 5: batchnorm normalize in place
// ---------------------------------------------------------------------------
__global__ void norm_kernel(float* __restrict__ out,
                            const float* __restrict__ gamma,
                            const float* __restrict__ beta, int n) {
    __shared__ float s_scale[DD], s_shift[DD];
    int tid = threadIdx.x;
    if (tid < DD) {
        float inv_n = 1.0f / (float)n;
        float m   = g_stats[tid] * inv_n;
        float var = g_stats[DD + tid] * inv_n - m * m;
        float sc  = gamma[tid] * rsqrtf(var + BN_EPS);
        s_scale[tid] = sc;
        s_shift[tid] = beta[tid] - m * sc;
    }
    __syncthreads();

    size_t total4 = (size_t)n * (DD / 4);
    size_t stride = (size_t)gridDim.x * blockDim.x;
    float4* out4 = (float4*)out;
    for (size_t i = (size_t)blockIdx.x * blockDim.x + tid; i < total4; i += stride) {
        int c = ((int)(i & 31)) * 4;   // column of first element in this float4
        float4 v = out4[i];
        v.x = fmaf(v.x, s_scale[c + 0], s_shift[c + 0]);
        v.y = fmaf(v.y, s_scale[c + 1], s_shift[c + 1]);
        v.z = fmaf(v.z, s_scale[c + 2], s_shift[c + 2]);
        v.w = fmaf(v.w, s_scale[c + 3], s_shift[c + 3]);
        out4[i] = v;
    }
}

// ---------------------------------------------------------------------------
// Launch
// Inputs: 0 x[N,128] f32 | 1 r[1001,128] f32 | 2 edge_index[2,E] i32
//         3 edge_type[E] i32 | 4 weight[128,128] f32 | 5 alpha[1002] f32
//         6 bias[128] f32 | 7 gamma[128] f32 | 8 beta[128] f32
// Output: out[N,128] f32 then r[1001,128] f32 (tuple flattened)
// ---------------------------------------------------------------------------
extern "C" void kernel_launch(void* const* d_in, const int* in_sizes, int n_in,
                              void* d_out, int out_size) {
    const float* x     = (const float*)d_in[0];
    const float* r     = (const float*)d_in[1];
    const int*   ei    = (const int*)d_in[2];
    const int*   et    = (const int*)d_in[3];
    const float* w     = (const float*)d_in[4];
    const float* alpha = (const float*)d_in[5];
    const float* gamma = (const float*)d_in[7];
    const float* beta  = (const float*)d_in[8];
    float* out = (float*)d_out;

    int n = in_sizes[0] / DD;
    int E = in_sizes[3];

    gemm_init_kernel<<<(n + 127) / 128, 256>>>(x, w, alpha, out, n);
    zero_stats_kernel<<<1, 256>>>();
    scatter_kernel<<<(E + 7) / 8, 256>>>(ei, et, alpha, out, E);
    stats_kernel<<<512, 128>>>(out, n);
    norm_kernel<<<1024, 256>>>(out, gamma, beta, n);

    // tuple element 2: r passthrough
    cudaMemcpyAsync(out + (size_t)n * DD, r,
                    (size_t)in_sizes[1] * sizeof(float),
                    cudaMemcpyDeviceToDevice);
}

// round 3
// speedup vs baseline: 1.1226x; 1.1226x over previous
#include <cuda_runtime.h>
#include <stdint.h>

#define DD 128
#define SELF_REL_IDX 1000
#define BN_EPS 1e-5f
#define MAX_N 100000

// Scratch (allocations are forbidden; __device__ globals are allowed)
__device__ float g_XW[(size_t)MAX_N * DD];
__device__ float g_stats[2 * DD];   // [0..127] sum, [128..255] sumsq

// ---------------------------------------------------------------------------
// Kernel 1: XW = x @ W  (fp32, 128x128 block tile, 8x8 per thread)
//           also out_init = 2*alpha[SELF_REL] * XW   (self-loop contribution)
// ---------------------------------------------------------------------------
__global__ void gemm_init_kernel(const float* __restrict__ x,
                                 const float* __restrict__ w,
                                 const float* __restrict__ alpha,
                                 float* __restrict__ out, int n) {
    __shared__ float xs[16][132];   // [k][row], padded to dodge bank conflicts
    __shared__ float ws[16][132];   // [k][col]
    const int tid = threadIdx.x;
    const int tx = tid & 15;        // col group
    const int ty = tid >> 4;        // row group
    const int row0 = blockIdx.x * 128;

    float acc[8][8];
#pragma unroll
    for (int i = 0; i < 8; i++)
#pragma unroll
        for (int j = 0; j < 8; j++) acc[i][j] = 0.f;

    for (int kb = 0; kb < 8; kb++) {
#pragma unroll
        for (int l = 0; l < 2; l++) {
            int idx = tid + l * 256;          // 0..511
            int r   = idx >> 2;               // 0..127
            int k4  = idx & 3;                // 0..3
            float4 v = make_float4(0.f, 0.f, 0.f, 0.f);
            if (row0 + r < n)
                v = *(const float4*)&x[(size_t)(row0 + r) * DD + kb * 16 + k4 * 4];
            xs[k4 * 4 + 0][r] = v.x;
            xs[k4 * 4 + 1][r] = v.y;
            xs[k4 * 4 + 2][r] = v.z;
            xs[k4 * 4 + 3][r] = v.w;
        }
#pragma unroll
        for (int l = 0; l < 2; l++) {
            int idx = tid + l * 256;          // 0..511
            int kk  = idx >> 5;               // 0..15
            int c4  = idx & 31;               // 0..31
            float4 v = *(const float4*)&w[(size_t)(kb * 16 + kk) * DD + c4 * 4];
            *(float4*)&ws[kk][c4 * 4] = v;
        }
        __syncthreads();

#pragma unroll
        for (int kk = 0; kk < 16; kk++) {
            float xr[8], wr[8];
            *(float4*)&xr[0] = *(const float4*)&xs[kk][ty * 8];
            *(float4*)&xr[4] = *(const float4*)&xs[kk][ty * 8 + 4];
            *(float4*)&wr[0] = *(const float4*)&ws[kk][tx * 8];
            *(float4*)&wr[4] = *(const float4*)&ws[kk][tx * 8 + 4];
#pragma unroll
            for (int i = 0; i < 8; i++)
#pragma unroll
                for (int j = 0; j < 8; j++)
                    acc[i][j] = fmaf(xr[i], wr[j], acc[i][j]);
        }
        __syncthreads();
    }

    const float s2 = 2.0f * __ldg(&alpha[SELF_REL_IDX]);
#pragma unroll
    for (int i = 0; i < 8; i++) {
        int row = row0 + ty * 8 + i;
        if (row >= n) break;
        size_t base = (size_t)row * DD + tx * 8;
        float4 a0 = make_float4(acc[i][0], acc[i][1], acc[i][2], acc[i][3]);
        float4 a1 = make_float4(acc[i][4], acc[i][5], acc[i][6], acc[i][7]);
        *(float4*)&g_XW[base]     = a0;
        *(float4*)&g_XW[base + 4] = a1;
        float4 o0 = make_float4(s2 * a0.x, s2 * a0.y, s2 * a0.z, s2 * a0.w);
        float4 o1 = make_float4(s2 * a1.x, s2 * a1.y, s2 * a1.z, s2 * a1.w);
        *(float4*)&out[base]     = o0;
        *(float4*)&out[base + 4] = o1;
    }
}

// ---------------------------------------------------------------------------
// Kernel 2: zero the stats accumulator
// ---------------------------------------------------------------------------
__global__ void zero_stats_kernel() {
    g_stats[threadIdx.x] = 0.f;
}

// ---------------------------------------------------------------------------
// Kernel 3: edge scatter. One warp per edge:
//   out[row] += a * XW[col];  out[col] += a * XW[row]
// Vector fp32 reductions (red.global.add.v4.f32, sm_90+).
// ---------------------------------------------------------------------------
__global__ void scatter_kernel(const int* __restrict__ ei,
                               const int* __restrict__ et,
                               const float* __restrict__ alpha,
                               float* __restrict__ out, int E) {
    int gid  = blockIdx.x * blockDim.x + threadIdx.x;
    int e    = gid >> 5;
    if (e >= E) return;
    int lane = gid & 31;

    int rw = __ldg(&ei[e]);
    int cl = __ldg(&ei[(size_t)E + e]);
    float a = __ldg(&alpha[__ldg(&et[e])]);

    const float4 vc = *(const float4*)&g_XW[(size_t)cl * DD + lane * 4];
    const float4 vr = *(const float4*)&g_XW[(size_t)rw * DD + lane * 4];

    float* pr = out + (size_t)rw * DD + lane * 4;
    float* pc = out + (size_t)cl * DD + lane * 4;

    asm volatile("red.global.add.v4.f32 [%0], {%1,%2,%3,%4};"
                 :: "l"(pr), "f"(a * vc.x), "f"(a * vc.y), "f"(a * vc.z), "f"(a * vc.w)
                 : "memory");
    asm volatile("red.global.add.v4.f32 [%0], {%1,%2,%3,%4};"
                 :: "l"(pc), "f"(a * vr.x), "f"(a * vr.y), "f"(a * vr.z), "f"(a * vr.w)
                 : "memory");
}

// ---------------------------------------------------------------------------
// Kernel 4: per-column sum / sum-of-squares (coalesced float4, ILP=2,
// shared-memory block reduction, one global atomic per (block,column)).
// ---------------------------------------------------------------------------
__global__ void stats_kernel(const float* __restrict__ out, int n) {
    __shared__ float sh_sum[DD];
    __shared__ float sh_sq[DD];
    const int tid = threadIdx.x;     // 256 threads
    if (tid < DD) { sh_sum[tid] = 0.f; sh_sq[tid] = 0.f; }
    __syncthreads();

    const float4* out4 = (const float4*)out;
    const size_t total4 = (size_t)n * (DD / 4);
    const size_t stride = (size_t)gridDim.x * blockDim.x;

    // thread's float4 index always has the same column group: (idx & 31)
    float s0 = 0.f, s1 = 0.f, s2 = 0.f, s3 = 0.f;
    float q0 = 0.f, q1 = 0.f, q2 = 0.f, q3 = 0.f;

    size_t i = (size_t)blockIdx.x * blockDim.x + tid;
    for (; i + stride < total4; i += 2 * stride) {
        float4 a = out4[i];
        float4 b = out4[i + stride];
        s0 += a.x + b.x; s1 += a.y + b.y; s2 += a.z + b.z; s3 += a.w + b.w;
        q0 = fmaf(a.x, a.x, q0); q0 = fmaf(b.x, b.x, q0);
        q1 = fmaf(a.y, a.y, q1); q1 = fmaf(b.y, b.y, q1);
        q2 = fmaf(a.z, a.z, q2); q2 = fmaf(b.z, b.z, q2);
        q3 = fmaf(a.w, a.w, q3); q3 = fmaf(b.w, b.w, q3);
    }
    if (i < total4) {
        float4 a = out4[i];
        s0 += a.x; s1 += a.y; s2 += a.z; s3 += a.w;
        q0 = fmaf(a.x, a.x, q0); q1 = fmaf(a.y, a.y, q1);
        q2 = fmaf(a.z, a.z, q2); q3 = fmaf(a.w, a.w, q3);
    }

    const int c = (tid & 31) * 4;    // column group is grid-stride invariant
    atomicAdd(&sh_sum[c + 0], s0); atomicAdd(&sh_sum[c + 1], s1);
    atomicAdd(&sh_sum[c + 2], s2); atomicAdd(&sh_sum[c + 3], s3);
    atomicAdd(&sh_sq[c + 0], q0);  atomicAdd(&sh_sq[c + 1], q1);
    atomicAdd(&sh_sq[c + 2], q2);  atomicAdd(&sh_sq[c + 3], q3);
    __syncthreads();

    if (tid < DD) {
        atomicAdd(&g_stats[tid], sh_sum[tid]);
        atomicAdd(&g_stats[DD + tid], sh_sq[tid]);
    }
}

// ---------------------------------------------------------------------------
// Kernel 5: batchnorm normalize in place
// ---------------------------------------------------------------------------
__global__ void norm_kernel(float* __restrict__ out,
                            const float* __restrict__ gamma,
                            const float* __restrict__ beta, int n) {
    __shared__ float s_scale[DD], s_shift[DD];
    int tid = threadIdx.x;
    if (tid < DD) {
        float inv_n = 1.0f / (float)n;
        float m   = g_stats[tid] * inv_n;
        float var = g_stats[DD + tid] * inv_n - m * m;
        float sc  = gamma[tid] * rsqrtf(var + BN_EPS);
        s_scale[tid] = sc;
        s_shift[tid] = beta[tid] - m * sc;
    }
    __syncthreads();

    size_t total4 = (size_t)n * (DD / 4);
    size_t stride = (size_t)gridDim.x * blockDim.x;
    float4* out4 = (float4*)out;
    for (size_t i = (size_t)blockIdx.x * blockDim.x + tid; i < total4; i += stride) {
        int c = ((int)(i & 31)) * 4;
        float4 v = out4[i];
        v.x = fmaf(v.x, s_scale[c + 0], s_shift[c + 0]);
        v.y = fmaf(v.y, s_scale[c + 1], s_shift[c + 1]);
        v.z = fmaf(v.z, s_scale[c + 2], s_shift[c + 2]);
        v.w = fmaf(v.w, s_scale[c + 3], s_shift[c + 3]);
        out4[i] = v;
    }
}

// ---------------------------------------------------------------------------
// Launch
// Inputs: 0 x[N,128] f32 | 1 r[1001,128] f32 | 2 edge_index[2,E] i32
//         3 edge_type[E] i32 | 4 weight[128,128] f32 | 5 alpha[1002] f32
//         6 bias[128] f32 | 7 gamma[128] f32 | 8 beta[128] f32
// Output: out[N,128] f32 then r[1001,128] f32 (tuple flattened)
// ---------------------------------------------------------------------------
extern "C" void kernel_launch(void* const* d_in, const int* in_sizes, int n_in,
                              void* d_out, int out_size) {
    const float* x     = (const float*)d_in[0];
    const float* r     = (const float*)d_in[1];
    const int*   ei    = (const int*)d_in[2];
    const int*   et    = (const int*)d_in[3];
    const float* w     = (const float*)d_in[4];
    const float* alpha = (const float*)d_in[5];
    const float* gamma = (const float*)d_in[7];
    const float* beta  = (const float*)d_in[8];
    float* out = (float*)d_out;

    int n = in_sizes[0] / DD;
    int E = in_sizes[3];

    gemm_init_kernel<<<(n + 127) / 128, 256>>>(x, w, alpha, out, n);
    zero_stats_kernel<<<1, 256>>>();
    scatter_kernel<<<(E + 7) / 8, 256>>>(ei, et, alpha, out, E);
    stats_kernel<<<592, 256>>>(out, n);
    norm_kernel<<<1184, 256>>>(out, gamma, beta, n);

    // tuple element 2: r passthrough
    cudaMemcpyAsync(out + (size_t)n * DD, r,
                    (size_t)in_sizes[1] * sizeof(float),
                    cudaMemcpyDeviceToDevice);
}

// round 4
// speedup vs baseline: 1.4572x; 1.2981x over previous
#include <cuda_runtime.h>
#include <stdint.h>

#define DD 128
#define SELF_REL_IDX 1000
#define BN_EPS 1e-5f
#define MAX_N 100000
#define MAX_E 1600000

// Scratch (__device__ globals; allocations are forbidden)
__device__ float g_XW[(size_t)MAX_N * DD];           // 51.2 MB
__device__ int2  g_adj[(size_t)2 * MAX_E];           // 25.6 MB  {nbr, alpha-bits}
__device__ int   g_deg[MAX_N];
__device__ int   g_rowptr[MAX_N + 1];
__device__ int   g_cursor[MAX_N];
__device__ int   g_boff[128];                        // block offsets for scan
__device__ float g_stats[2 * DD];                    // col sums / sumsq

// ---------------------------------------------------------------------------
// Kernel 1: XW = x @ W  (fp32, 128x128 tile, 8x8 per thread)
// ---------------------------------------------------------------------------
__global__ void gemm_kernel(const float* __restrict__ x,
                            const float* __restrict__ w, int n) {
    __shared__ float xs[16][132];
    __shared__ float ws[16][132];
    const int tid = threadIdx.x;
    const int tx = tid & 15;
    const int ty = tid >> 4;
    const int row0 = blockIdx.x * 128;

    float acc[8][8];
#pragma unroll
    for (int i = 0; i < 8; i++)
#pragma unroll
        for (int j = 0; j < 8; j++) acc[i][j] = 0.f;

    for (int kb = 0; kb < 8; kb++) {
#pragma unroll
        for (int l = 0; l < 2; l++) {
            int idx = tid + l * 256;
            int r   = idx >> 2;
            int k4  = idx & 3;
            float4 v = make_float4(0.f, 0.f, 0.f, 0.f);
            if (row0 + r < n)
                v = *(const float4*)&x[(size_t)(row0 + r) * DD + kb * 16 + k4 * 4];
            xs[k4 * 4 + 0][r] = v.x;
            xs[k4 * 4 + 1][r] = v.y;
            xs[k4 * 4 + 2][r] = v.z;
            xs[k4 * 4 + 3][r] = v.w;
        }
#pragma unroll
        for (int l = 0; l < 2; l++) {
            int idx = tid + l * 256;
            int kk  = idx >> 5;
            int c4  = idx & 31;
            *(float4*)&ws[kk][c4 * 4] =
                *(const float4*)&w[(size_t)(kb * 16 + kk) * DD + c4 * 4];
        }
        __syncthreads();

#pragma unroll
        for (int kk = 0; kk < 16; kk++) {
            float xr[8], wr[8];
            *(float4*)&xr[0] = *(const float4*)&xs[kk][ty * 8];
            *(float4*)&xr[4] = *(const float4*)&xs[kk][ty * 8 + 4];
            *(float4*)&wr[0] = *(const float4*)&ws[kk][tx * 8];
            *(float4*)&wr[4] = *(const float4*)&ws[kk][tx * 8 + 4];
#pragma unroll
            for (int i = 0; i < 8; i++)
#pragma unroll
                for (int j = 0; j < 8; j++)
                    acc[i][j] = fmaf(xr[i], wr[j], acc[i][j]);
        }
        __syncthreads();
    }

#pragma unroll
    for (int i = 0; i < 8; i++) {
        int row = row0 + ty * 8 + i;
        if (row >= n) break;
        size_t base = (size_t)row * DD + tx * 8;
        *(float4*)&g_XW[base]     = make_float4(acc[i][0], acc[i][1], acc[i][2], acc[i][3]);
        *(float4*)&g_XW[base + 4] = make_float4(acc[i][4], acc[i][5], acc[i][6], acc[i][7]);
    }
}

// ---------------------------------------------------------------------------
// Kernel 2: zero degree counters + stats
// ---------------------------------------------------------------------------
__global__ void zero_kernel(int n) {
    int i = blockIdx.x * blockDim.x + threadIdx.x;
    if (i < n) g_deg[i] = 0;
    if (i < 2 * DD) g_stats[i] = 0.f;
}

// ---------------------------------------------------------------------------
// Kernel 3: degree histogram (both directions)
// ---------------------------------------------------------------------------
__global__ void hist_kernel(const int* __restrict__ ei, int E) {
    int e = blockIdx.x * blockDim.x + threadIdx.x;
    if (e >= E) return;
    atomicAdd(&g_deg[__ldg(&ei[e])], 1);
    atomicAdd(&g_deg[__ldg(&ei[(size_t)E + e])], 1);
}

// ---------------------------------------------------------------------------
// Kernels 4a/4b/4c: exclusive prefix sum over degrees -> rowptr, cursor
// ---------------------------------------------------------------------------
__global__ void scanA_kernel(int n) {           // per-block sums (1024/block)
    __shared__ int sh[1024];
    int idx = blockIdx.x * 1024 + threadIdx.x;
    int v = (idx < n) ? g_deg[idx] : 0;
    sh[threadIdx.x] = v;
    __syncthreads();
    for (int off = 512; off > 0; off >>= 1) {
        if (threadIdx.x < off) sh[threadIdx.x] += sh[threadIdx.x + off];
        __syncthreads();
    }
    if (threadIdx.x == 0) g_boff[blockIdx.x] = sh[0];
}

__global__ void scanB_kernel(int nblocks, int n) {  // scan block sums (1 thread)
    if (threadIdx.x == 0 && blockIdx.x == 0) {
        int run = 0;
        for (int i = 0; i < nblocks; i++) {
            int t = g_boff[i];
            g_boff[i] = run;
            run += t;
        }
        g_rowptr[n] = run;
    }
}

__global__ void scanC_kernel(int n) {           // intra-block scan + offset
    __shared__ int sh[1024];
    int idx = blockIdx.x * 1024 + threadIdx.x;
    int v = (idx < n) ? g_deg[idx] : 0;
    sh[threadIdx.x] = v;
    __syncthreads();
    // Hillis-Steele inclusive scan
    for (int off = 1; off < 1024; off <<= 1) {
        int add = (threadIdx.x >= off) ? sh[threadIdx.x - off] : 0;
        __syncthreads();
        sh[threadIdx.x] += add;
        __syncthreads();
    }
    if (idx < n) {
        int excl = g_boff[blockIdx.x] + sh[threadIdx.x] - v;
        g_rowptr[idx] = excl;
        g_cursor[idx] = excl;
    }
}

// ---------------------------------------------------------------------------
// Kernel 5: fill adjacency (both directions, alpha packed per entry)
// ---------------------------------------------------------------------------
__global__ void fill_kernel(const int* __restrict__ ei,
                            const int* __restrict__ et,
                            const float* __restrict__ alpha, int E) {
    int e = blockIdx.x * blockDim.x + threadIdx.x;
    if (e >= E) return;
    int rw = __ldg(&ei[e]);
    int cl = __ldg(&ei[(size_t)E + e]);
    int ab = __float_as_int(__ldg(&alpha[__ldg(&et[e])]));
    int p1 = atomicAdd(&g_cursor[rw], 1);
    g_adj[p1] = make_int2(cl, ab);
    int p2 = atomicAdd(&g_cursor[cl], 1);
    g_adj[p2] = make_int2(rw, ab);
}

// ---------------------------------------------------------------------------
// Kernel 6: gather. One warp per node:
//   out[i] = 2*a_self*XW[i] + sum_nbr a*XW[nbr]
// Fused BN stats (per-lane column accumulators -> shared -> global).
// ---------------------------------------------------------------------------
__global__ void gather_kernel(float* __restrict__ out,
                              const float* __restrict__ alpha, int n) {
    __shared__ float sh_sum[DD];
    __shared__ float sh_sq[DD];
    const int tid  = threadIdx.x;
    const int lane = tid & 31;
    if (tid < DD) { sh_sum[tid] = 0.f; sh_sq[tid] = 0.f; }
    __syncthreads();

    const float s2 = 2.0f * __ldg(&alpha[SELF_REL_IDX]);
    const float4* XW4 = (const float4*)g_XW;
    const int warpsTotal = (gridDim.x * blockDim.x) >> 5;
    int w = (blockIdx.x * blockDim.x + tid) >> 5;

    float st0 = 0.f, st1 = 0.f, st2 = 0.f, st3 = 0.f;
    float sq0 = 0.f, sq1 = 0.f, sq2 = 0.f, sq3 = 0.f;

    for (int node = w; node < n; node += warpsTotal) {
        float4 self = XW4[(size_t)node * 32 + lane];
        float4 acc = make_float4(s2 * self.x, s2 * self.y, s2 * self.z, s2 * self.w);

        int beg = __ldg(&g_rowptr[node]);
        int end = __ldg(&g_rowptr[node + 1]);
        int j = beg;
        for (; j + 1 < end; j += 2) {
            int2 e0 = __ldg(&g_adj[j]);
            int2 e1 = __ldg(&g_adj[j + 1]);
            float a0 = __int_as_float(e0.y);
            float a1 = __int_as_float(e1.y);
            float4 v0 = XW4[(size_t)e0.x * 32 + lane];
            float4 v1 = XW4[(size_t)e1.x * 32 + lane];
            acc.x = fmaf(a0, v0.x, acc.x); acc.y = fmaf(a0, v0.y, acc.y);
            acc.z = fmaf(a0, v0.z, acc.z); acc.w = fmaf(a0, v0.w, acc.w);
            acc.x = fmaf(a1, v1.x, acc.x); acc.y = fmaf(a1, v1.y, acc.y);
            acc.z = fmaf(a1, v1.z, acc.z); acc.w = fmaf(a1, v1.w, acc.w);
        }
        if (j < end) {
            int2 e0 = __ldg(&g_adj[j]);
            float a0 = __int_as_float(e0.y);
            float4 v0 = XW4[(size_t)e0.x * 32 + lane];
            acc.x = fmaf(a0, v0.x, acc.x); acc.y = fmaf(a0, v0.y, acc.y);
            acc.z = fmaf(a0, v0.z, acc.z); acc.w = fmaf(a0, v0.w, acc.w);
        }

        ((float4*)out)[(size_t)node * 32 + lane] = acc;

        st0 += acc.x; st1 += acc.y; st2 += acc.z; st3 += acc.w;
        sq0 = fmaf(acc.x, acc.x, sq0); sq1 = fmaf(acc.y, acc.y, sq1);
        sq2 = fmaf(acc.z, acc.z, sq2); sq3 = fmaf(acc.w, acc.w, sq3);
    }

    const int c = lane * 4;
    atomicAdd(&sh_sum[c + 0], st0); atomicAdd(&sh_sum[c + 1], st1);
    atomicAdd(&sh_sum[c + 2], st2); atomicAdd(&sh_sum[c + 3], st3);
    atomicAdd(&sh_sq[c + 0], sq0);  atomicAdd(&sh_sq[c + 1], sq1);
    atomicAdd(&sh_sq[c + 2], sq2);  atomicAdd(&sh_sq[c + 3], sq3);
    __syncthreads();

    if (tid < DD) {
        atomicAdd(&g_stats[tid], sh_sum[tid]);
        atomicAdd(&g_stats[DD + tid], sh_sq[tid]);
    }
}

// ---------------------------------------------------------------------------
// Kernel 7: batchnorm normalize in place
// ---------------------------------------------------------------------------
__global__ void norm_kernel(float* __restrict__ out,
                            const float* __restrict__ gamma,
                            const float* __restrict__ beta, int n) {
    __shared__ float s_scale[DD], s_shift[DD];
    int tid = threadIdx.x;
    if (tid < DD) {
        float inv_n = 1.0f / (float)n;
        float m   = g_stats[tid] * inv_n;
        float var = g_stats[DD + tid] * inv_n - m * m;
        float sc  = gamma[tid] * rsqrtf(var + BN_EPS);
        s_scale[tid] = sc;
        s_shift[tid] = beta[tid] - m * sc;
    }
    __syncthreads();

    size_t total4 = (size_t)n * (DD / 4);
    size_t stride = (size_t)gridDim.x * blockDim.x;
    float4* out4 = (float4*)out;
    for (size_t i = (size_t)blockIdx.x * blockDim.x + tid; i < total4; i += stride) {
        int c = ((int)(i & 31)) * 4;
        float4 v = out4[i];
        v.x = fmaf(v.x, s_scale[c + 0], s_shift[c + 0]);
        v.y = fmaf(v.y, s_scale[c + 1], s_shift[c + 1]);
        v.z = fmaf(v.z, s_scale[c + 2], s_shift[c + 2]);
        v.w = fmaf(v.w, s_scale[c + 3], s_shift[c + 3]);
        out4[i] = v;
    }
}

// ---------------------------------------------------------------------------
// Launch
// Inputs: 0 x[N,128] f32 | 1 r[1001,128] f32 | 2 edge_index[2,E] i32
//         3 edge_type[E] i32 | 4 weight[128,128] f32 | 5 alpha[1002] f32
//         6 bias[128] f32 | 7 gamma[128] f32 | 8 beta[128] f32
// ---------------------------------------------------------------------------
extern "C" void kernel_launch(void* const* d_in, const int* in_sizes, int n_in,
                              void* d_out, int out_size) {
    const float* x     = (const float*)d_in[0];
    const float* r     = (const float*)d_in[1];
    const int*   ei    = (const int*)d_in[2];
    const int*   et    = (const int*)d_in[3];
    const float* w     = (const float*)d_in[4];
    const float* alpha = (const float*)d_in[5];
    const float* gamma = (const float*)d_in[7];
    const float* beta  = (const float*)d_in[8];
    float* out = (float*)d_out;

    int n = in_sizes[0] / DD;
    int E = in_sizes[3];
    int nScanBlocks = (n + 1023) / 1024;

    gemm_kernel<<<(n + 127) / 128, 256>>>(x, w, n);
    zero_kernel<<<(n + 255) / 256, 256>>>(n);
    hist_kernel<<<(E + 255) / 256, 256>>>(ei, E);
    scanA_kernel<<<nScanBlocks, 1024>>>(n);
    scanB_kernel<<<1, 32>>>(nScanBlocks, n);
    scanC_kernel<<<nScanBlocks, 1024>>>(n);
    fill_kernel<<<(E + 255) / 256, 256>>>(ei, et, alpha, E);
    gather_kernel<<<1184, 256>>>(out, alpha, n);
    norm_kernel<<<1184, 256>>>(out, gamma, beta, n);

    cudaMemcpyAsync(out + (size_t)n * DD, r,
                    (size_t)in_sizes[1] * sizeof(float),
                    cudaMemcpyDeviceToDevice);
}